// round 3
// baseline (speedup 1.0000x reference)
#include <cuda_runtime.h>

// RBF trainable activation:
//   out[b,c,h,w] = sum_j w[c,j] * exp(-(x[b,c,h,w]-mu_j)^2 / (2 sigma^2))
// with mu_j = linspace(-1,1,63), sigma = 1/31.
//
// 3-stage:
//   A : windowed exp -> (f, f') at 513 Hermite nodes over [-1.3, 1.3]  (global)
//   A2: Hermite nodes -> 512 power-basis cubic coefs per channel       (global)
//   B : per-block prologue expands cubic -> 4096-interval LINEAR table
//       in smem (float2 = 8B/lookup, halves LDS traffic vs float4),
//       then streams the slab: LDS.64 + 2 FMA per element.
// Outside [-1.3, 1.3] the true function is < 2e-18 -> clamping is exact.

#define NW 63
#define NCH 64
#define NODES 513
#define NINTERVALS 512
#define HW 9216              // 96*96
#define SLABS 1024           // 16*64

#define XLO (-1.30f)
#define XHI (1.30f)
#define HSTEP ((XHI - XLO) / (float)NINTERVALS)

// fine linear table
#define NF 4096
#define INV_HF ((float)NF / (XHI - XLO))       // 1575.3846
#define XOFF 2048.0f                           // -XLO * INV_HF (exact)

// sigma = 1/31
#define INV_2S2 480.5f
#define INV_S2  961.0f
#define SIG     (1.0f / 31.0f)

static __device__ float2 g_nodes[NCH][NODES];
static __device__ float4 g_coef[NCH][NINTERVALS];

// ---------------------------------------------------------------------------
// Kernel A: (f, f') at Hermite nodes, windowed to +-8 sigma (tail < 1e-14).
// ---------------------------------------------------------------------------
__global__ void build_nodes_kernel(const float* __restrict__ w) {
    int c = blockIdx.x;
    int n = blockIdx.y * blockDim.x + threadIdx.x;
    if (n >= NODES) return;

    float x = XLO + (float)n * HSTEP;
    float jc = (x + 1.0f) * 31.0f;
    int j0 = (int)ceilf(jc - 8.0f);
    int j1 = (int)floorf(jc + 8.0f);
    if (j0 < 0) j0 = 0;
    if (j1 > NW - 1) j1 = NW - 1;

    float f = 0.0f, fp = 0.0f;
    for (int j = j0; j <= j1; ++j) {
        float mu = -1.0f + (float)j * SIG;
        float d = x - mu;
        float e = __expf(-INV_2S2 * d * d) * w[c * NW + j];
        f += e;
        fp -= INV_S2 * d * e;
    }
    g_nodes[c][n] = make_float2(f, fp);
}

// ---------------------------------------------------------------------------
// Kernel A2: Hermite nodes -> power-basis cubic per coarse interval.
// p(t) = a + b t + c t^2 + d t^3, t in [0,1].
// ---------------------------------------------------------------------------
__global__ void build_coef_kernel() {
    int c = blockIdx.x;
    int i = blockIdx.y * blockDim.x + threadIdx.x;
    if (i >= NINTERVALS) return;
    float2 n0 = g_nodes[c][i];
    float2 n1 = g_nodes[c][i + 1];
    float m0 = n0.y * HSTEP, m1 = n1.y * HSTEP;
    float del = n1.x - n0.x;
    g_coef[c][i] = make_float4(n0.x,
                               m0,
                               3.0f * del - 2.0f * m0 - m1,
                               -2.0f * del + m0 + m1);
}

// ---------------------------------------------------------------------------
// Kernel B: stream one (b,c) slab per block.
// ---------------------------------------------------------------------------
__global__ void __launch_bounds__(256) rbf_act_kernel(const float* __restrict__ x,
                                                      float* __restrict__ out) {
    __shared__ float2 tab[NF];    // 32 KB: (f, f1 - f0) per fine interval

    int s = blockIdx.x;           // slab = b*64 + c (matches linear layout)
    int c = s & (NCH - 1);
    int tid = threadIdx.x;

    // Prologue: expand cubic -> fine linear table. Fine node n lies in coarse
    // interval n>>3 at t = (n&7)/8; node 4096 is t=1 of interval 511 (exact
    // Hermite endpoint), so f1 for i<=4095 always evaluates in-range.
    #pragma unroll 4
    for (int i = tid; i < NF; i += 256) {
        float4 cf = g_coef[c][i >> 3];
        float t0 = (float)(i & 7) * 0.125f;
        float t1 = t0 + 0.125f;
        float f0 = fmaf(fmaf(fmaf(cf.w, t0, cf.z), t0, cf.y), t0, cf.x);
        float f1 = fmaf(fmaf(fmaf(cf.w, t1, cf.z), t1, cf.y), t1, cf.x);
        tab[i] = make_float2(f0, f1 - f0);
    }
    __syncthreads();

    const float4* __restrict__ xin = (const float4*)(x + (size_t)s * HW);
    float4* __restrict__ o = (float4*)(out + (size_t)s * HW);

    #pragma unroll 3
    for (int i = tid; i < HW / 4; i += 256) {
        float4 v = xin[i];
        float4 r;
        {
            float t = fminf(fmaxf(fmaf(v.x, INV_HF, XOFF), 0.0f), 4095.999f);
            int idx = (int)t; float fr = t - (float)idx;
            float2 e = tab[idx];
            r.x = fmaf(fr, e.y, e.x);
        }
        {
            float t = fminf(fmaxf(fmaf(v.y, INV_HF, XOFF), 0.0f), 4095.999f);
            int idx = (int)t; float fr = t - (float)idx;
            float2 e = tab[idx];
            r.y = fmaf(fr, e.y, e.x);
        }
        {
            float t = fminf(fmaxf(fmaf(v.z, INV_HF, XOFF), 0.0f), 4095.999f);
            int idx = (int)t; float fr = t - (float)idx;
            float2 e = tab[idx];
            r.z = fmaf(fr, e.y, e.x);
        }
        {
            float t = fminf(fmaxf(fmaf(v.w, INV_HF, XOFF), 0.0f), 4095.999f);
            int idx = (int)t; float fr = t - (float)idx;
            float2 e = tab[idx];
            r.w = fmaf(fr, e.y, e.x);
        }
        o[i] = r;
    }
}

// ---------------------------------------------------------------------------
extern "C" void kernel_launch(void* const* d_in, const int* in_sizes, int n_in,
                              void* d_out, int out_size) {
    const float* x = (const float*)d_in[0];
    const float* w = (const float*)d_in[1];
    if (in_sizes[0] == NCH * NW) {       // defensive input-order check
        x = (const float*)d_in[1];
        w = (const float*)d_in[0];
    }

    build_nodes_kernel<<<dim3(NCH, 3), 192>>>(w);
    build_coef_kernel<<<dim3(NCH, 2), 256>>>();
    rbf_act_kernel<<<SLABS, 256>>>(x, (float*)d_out);
}